// round 1
// baseline (speedup 1.0000x reference)
#include <cuda_runtime.h>
#include <math.h>
#include <stdint.h>

#define N_NODESC 50000
#define N_EDGESC 800000
#define HIDDENC  128
#define MSGC     64
#define GATESC   256    // 4*MSG
#define KTOT     192    // HIDDEN + MSG

// ---------------- device scratch (no allocations allowed) ----------------
struct Scratch {
    float acc0[(size_t)N_NODESC * HIDDENC];
    float acc1[(size_t)N_NODESC * HIDDENC];
    float cnt0[N_NODESC];
    float cnt1[N_NODESC];
};
__device__ Scratch g_S;
__device__ float g_WT[KTOT * GATESC];   // [k][r] transposed weights (Wih rows 0..127, Whh rows 128..191)
__device__ float g_bias[GATESC];        // b_ih + b_hh

// ---------------- prep: transpose W, combine bias ----------------
__global__ void prep_kernel(const float* __restrict__ W_ih, const float* __restrict__ W_hh,
                            const float* __restrict__ b_ih, const float* __restrict__ b_hh)
{
    int r = threadIdx.x;        // gate row 0..255
    int k = blockIdx.x;         // k 0..191
    float v;
    if (k < HIDDENC) v = W_ih[r * HIDDENC + k];
    else             v = W_hh[r * MSGC + (k - HIDDENC)];
    g_WT[k * GATESC + r] = v;
    if (k == 0) g_bias[r] = b_ih[r] + b_hh[r];
}

// ---------------- edge scatter: warp per edge, vector red ----------------
__global__ void __launch_bounds__(256) scatter_kernel(
    const float* __restrict__ feat,
    const int* __restrict__ src, const int* __restrict__ dst,
    float* __restrict__ acc, float* __restrict__ cnt)
{
    int warp = (blockIdx.x * 256 + threadIdx.x) >> 5;
    int lane = threadIdx.x & 31;
    if (warp >= N_EDGESC) return;
    int s = __ldg(src + warp);
    int d = __ldg(dst + warp);
    const float4* f4 = (const float4*)(feat + (size_t)s * HIDDENC);
    float4 v = f4[lane];
    float* a = acc + (size_t)d * HIDDENC + lane * 4;
    asm volatile("red.global.add.v4.f32 [%0], {%1, %2, %3, %4};"
                 :: "l"(a), "f"(v.x), "f"(v.y), "f"(v.z), "f"(v.w) : "memory");
    if (lane == 0) atomicAdd(cnt + d, 1.0f);
}

// ---------------- fused rst + gates GEMM + LSTM cell ----------------
#define NPB   64     // nodes per block
#define XPAD  68     // padded node stride for XT (272B rows: 16B aligned, bank-skewed)

struct SmemT {
    float Ws[128 * GATESC];   // 128KB: W stage (2 phases) then reused as gates[n][256]
    float XT[KTOT * XPAD];    // k-major X: rows 0..127 feat, 128..191 G_t
    float R[NPB * MSGC];      // R_t per node
    float bias[GATESC];
    float inv0[NPB], inv1[NPB], invA[NPB];
};

__device__ __forceinline__ float sigf(float x) { return 1.0f / (1.0f + __expf(-x)); }

__global__ void __launch_bounds__(256, 1) lstm_kernel(const float* __restrict__ feat,
                                                      float* __restrict__ out)
{
    extern __shared__ float smraw[];
    SmemT* sm = (SmemT*)smraw;
    const int t  = threadIdx.x;
    const int n0 = blockIdx.x * NPB;

    // per-node scalars
    if (t < NPB) {
        int n = n0 + t;
        float c0 = 0.0f, c1 = 0.0f;
        if (n < N_NODESC) { c0 = g_S.cnt0[n]; c1 = g_S.cnt1[n]; }
        sm->inv0[t] = 1.0f / fmaxf(c0, 1.0f);
        sm->inv1[t] = 1.0f / fmaxf(c1, 1.0f);
        float has = (c0 > 0.0f ? 1.0f : 0.0f) + (c1 > 0.0f ? 1.0f : 0.0f);
        sm->invA[t] = 1.0f / fmaxf(has, 1.0f);
    }
    sm->bias[t] = g_bias[t];
    __syncthreads();

    // stage XT (feat rows 0..127, G_t rows 128..191) and R
    #pragma unroll
    for (int i = 0; i < (NPB * HIDDENC) / 256; i++) {   // 32 iters
        int idx = t + i * 256;
        int nn = idx >> 7;
        int c  = idx & 127;
        int n  = n0 + nn;
        float fv = 0.0f, a0 = 0.0f, a1 = 0.0f;
        if (n < N_NODESC) {
            fv = feat[(size_t)n * HIDDENC + c];
            a0 = g_S.acc0[(size_t)n * HIDDENC + c];
            a1 = g_S.acc1[(size_t)n * HIDDENC + c];
        }
        sm->XT[c * XPAD + nn] = fv;
        float r = (a0 * sm->inv0[nn] + a1 * sm->inv1[nn]) * sm->invA[nn];
        if (c < MSGC) sm->XT[(HIDDENC + c) * XPAD + nn] = r;
        else          sm->R[nn * MSGC + (c - MSGC)] = r;
    }

    // stage W phase 1: WihT rows 0..127 (coalesced, conflict-free float4)
    #pragma unroll
    for (int i = 0; i < (128 * GATESC) / (256 * 4); i++) {   // 32 iters
        int idx = t + i * 256;
        ((float4*)sm->Ws)[idx] = ((const float4*)g_WT)[idx];
    }
    __syncthreads();

    const int tx = t & 63;    // gate group: rows tx*4..tx*4+3
    const int ty = t >> 6;    // node group: nodes ty*16..ty*16+15

    float acc[4][16];
    {
        float4 bv = *(float4*)&sm->bias[tx * 4];
        #pragma unroll
        for (int j = 0; j < 16; j++) {
            acc[0][j] = bv.x; acc[1][j] = bv.y; acc[2][j] = bv.z; acc[3][j] = bv.w;
        }
    }

    const float* Xbase = &sm->XT[ty * 16];

    // phase 1: k = 0..127 (feat @ W_ih^T)
    #pragma unroll 4
    for (int k = 0; k < HIDDENC; k++) {
        float4 w = *(float4*)&sm->Ws[k * GATESC + tx * 4];
        const float* xr = Xbase + k * XPAD;
        float xv[16];
        *(float4*)&xv[0]  = *(const float4*)(xr);
        *(float4*)&xv[4]  = *(const float4*)(xr + 4);
        *(float4*)&xv[8]  = *(const float4*)(xr + 8);
        *(float4*)&xv[12] = *(const float4*)(xr + 12);
        #pragma unroll
        for (int j = 0; j < 16; j++) {
            acc[0][j] = fmaf(w.x, xv[j], acc[0][j]);
            acc[1][j] = fmaf(w.y, xv[j], acc[1][j]);
            acc[2][j] = fmaf(w.z, xv[j], acc[2][j]);
            acc[3][j] = fmaf(w.w, xv[j], acc[3][j]);
        }
    }
    __syncthreads();

    // stage W phase 2: WhhT rows 128..191
    #pragma unroll
    for (int i = 0; i < (MSGC * GATESC) / (256 * 4); i++) {   // 16 iters
        int idx = t + i * 256;
        ((float4*)sm->Ws)[idx] = ((const float4*)g_WT)[(128 * GATESC) / 4 + idx];
    }
    __syncthreads();

    // phase 2: k = 0..63 (G_t @ W_hh^T)
    #pragma unroll 4
    for (int k = 0; k < MSGC; k++) {
        float4 w = *(float4*)&sm->Ws[k * GATESC + tx * 4];
        const float* xr = Xbase + (HIDDENC + k) * XPAD;
        float xv[16];
        *(float4*)&xv[0]  = *(const float4*)(xr);
        *(float4*)&xv[4]  = *(const float4*)(xr + 4);
        *(float4*)&xv[8]  = *(const float4*)(xr + 8);
        *(float4*)&xv[12] = *(const float4*)(xr + 12);
        #pragma unroll
        for (int j = 0; j < 16; j++) {
            acc[0][j] = fmaf(w.x, xv[j], acc[0][j]);
            acc[1][j] = fmaf(w.y, xv[j], acc[1][j]);
            acc[2][j] = fmaf(w.z, xv[j], acc[2][j]);
            acc[3][j] = fmaf(w.w, xv[j], acc[3][j]);
        }
    }
    __syncthreads();   // everyone done reading Ws before we overwrite with gates

    // write gates node-major into Ws region (conflict-free float4)
    #pragma unroll
    for (int j = 0; j < 16; j++) {
        int n = ty * 16 + j;
        float4 gv = make_float4(acc[0][j], acc[1][j], acc[2][j], acc[3][j]);
        *(float4*)&sm->Ws[n * GATESC + tx * 4] = gv;
    }
    __syncthreads();

    // LSTM epilogue: 4 threads per node, 16 cols each
    {
        int n  = t >> 2;
        int j0 = (t & 3) * 16;
        if (n0 + n < N_NODESC) {
            float h[16], c[16];
            const float* gs = &sm->Ws[n * GATESC];
            #pragma unroll
            for (int jj = 0; jj < 16; jj++) {
                int j = j0 + jj;
                float gi = gs[j];
                float gf = gs[MSGC + j];
                float gg = gs[2 * MSGC + j];
                float go = gs[3 * MSGC + j];
                float Rv = sm->R[n * MSGC + j];
                float cc = sigf(gf) * Rv + sigf(gi) * tanhf(gg);
                c[jj] = cc;
                h[jj] = sigf(go) * tanhf(cc);
            }
            float* orow = out + (size_t)(n0 + n) * HIDDENC;
            #pragma unroll
            for (int q = 0; q < 4; q++) {
                *(float4*)&orow[j0 + q * 4]        = *(float4*)&h[q * 4];
                *(float4*)&orow[MSGC + j0 + q * 4] = *(float4*)&c[q * 4];
            }
        }
    }
}

// ---------------- launch ----------------
extern "C" void kernel_launch(void* const* d_in, const int* in_sizes, int n_in,
                              void* d_out, int out_size)
{
    const float* feat = (const float*)d_in[0];
    const int*   src0 = (const int*)d_in[1];
    const int*   dst0 = (const int*)d_in[2];
    const int*   src1 = (const int*)d_in[3];
    const int*   dst1 = (const int*)d_in[4];
    const float* W_ih = (const float*)d_in[5];
    const float* W_hh = (const float*)d_in[6];
    const float* b_ih = (const float*)d_in[7];
    const float* b_hh = (const float*)d_in[8];
    float* out = (float*)d_out;

    void* sp = nullptr;
    cudaGetSymbolAddress(&sp, g_S);
    float* acc0 = (float*)sp;
    float* acc1 = acc0 + (size_t)N_NODESC * HIDDENC;
    float* cnt0 = acc1 + (size_t)N_NODESC * HIDDENC;
    float* cnt1 = cnt0 + N_NODESC;

    cudaMemsetAsync(sp, 0, sizeof(Scratch), 0);

    prep_kernel<<<KTOT, GATESC>>>(W_ih, W_hh, b_ih, b_hh);

    scatter_kernel<<<N_EDGESC / 8, 256>>>(feat, src0, dst0, acc0, cnt0);
    scatter_kernel<<<N_EDGESC / 8, 256>>>(feat, src1, dst1, acc1, cnt1);

    const int smem = (int)sizeof(SmemT);
    cudaFuncSetAttribute(lstm_kernel, cudaFuncAttributeMaxDynamicSharedMemorySize, smem);
    int nblocks = (N_NODESC + NPB - 1) / NPB;
    lstm_kernel<<<nblocks, 256, smem>>>(feat, out);
}

// round 2
// speedup vs baseline: 1.4721x; 1.4721x over previous
#include <cuda_runtime.h>
#include <math.h>
#include <stdint.h>

#define N_NODESC 50000
#define N_EDGESC 800000
#define HIDDENC  128
#define MSGC     64
#define GATESC   256    // 4*MSG
#define NSEG     (2 * N_NODESC)     // flat segments: etype0 nodes then etype1 nodes
#define NEDGE_T  (2 * N_EDGESC)
#define SCAN_BS  512
#define SCAN_NB  ((NSEG + SCAN_BS - 1) / SCAN_BS)   // 196

// ---------------- device scratch (no dynamic allocation allowed) -------------
__device__ int   g_deg[NSEG];
__device__ int   g_start[NSEG];
__device__ int   g_cursor[NSEG];
__device__ int   g_bsum[SCAN_NB];
__device__ int   g_ssorted[NEDGE_T];
__device__ float g_rst[(size_t)N_NODESC * HIDDENC];     // (mean0+mean1)/n_active
__device__ float g_gates[(size_t)N_NODESC * GATESC];    // feat@Wih^T + bias (gemm1)
__device__ float g_WT[192 * GATESC];   // [k][r]: rows 0..127 Wih^T, 128..191 Whh^T
__device__ float g_bias[GATESC];

// ---------------- prep: transpose W, combine bias ----------------
__global__ void prep_kernel(const float* __restrict__ W_ih, const float* __restrict__ W_hh,
                            const float* __restrict__ b_ih, const float* __restrict__ b_hh)
{
    int r = threadIdx.x;        // gate row 0..255
    int k = blockIdx.x;         // k 0..191
    float v;
    if (k < HIDDENC) v = W_ih[r * HIDDENC + k];
    else             v = W_hh[r * MSGC + (k - HIDDENC)];
    g_WT[k * GATESC + r] = v;
    if (k == 0) g_bias[r] = b_ih[r] + b_hh[r];
}

// ---------------- CSR build ----------------
__global__ void __launch_bounds__(256) count_kernel(
    const int* __restrict__ dst0, const int* __restrict__ dst1)
{
    int e = blockIdx.x * 256 + threadIdx.x;
    if (e >= NEDGE_T) return;
    if (e < N_EDGESC) atomicAdd(&g_deg[dst0[e]], 1);
    else              atomicAdd(&g_deg[N_NODESC + dst1[e - N_EDGESC]], 1);
}

__global__ void __launch_bounds__(SCAN_BS) scanA_kernel()
{
    __shared__ int s[SCAN_BS];
    int tid = threadIdx.x;
    int i = blockIdx.x * SCAN_BS + tid;
    int v = (i < NSEG) ? g_deg[i] : 0;
    s[tid] = v;
    __syncthreads();
    #pragma unroll
    for (int off = 1; off < SCAN_BS; off <<= 1) {
        int x = (tid >= off) ? s[tid - off] : 0;
        __syncthreads();
        s[tid] += x;
        __syncthreads();
    }
    if (i < NSEG) g_start[i] = s[tid] - v;         // exclusive within block
    if (tid == SCAN_BS - 1) g_bsum[blockIdx.x] = s[tid];
}

__global__ void scanB_kernel()
{
    if (threadIdx.x == 0) {
        int acc = 0;
        for (int b = 0; b < SCAN_NB; b++) { int t = g_bsum[b]; g_bsum[b] = acc; acc += t; }
    }
}

__global__ void __launch_bounds__(SCAN_BS) scanC_kernel()
{
    int i = blockIdx.x * SCAN_BS + threadIdx.x;
    if (i < NSEG) {
        int v = g_start[i] + g_bsum[blockIdx.x];
        g_start[i] = v;
        g_cursor[i] = v;
    }
}

__global__ void __launch_bounds__(256) fill_kernel(
    const int* __restrict__ src0, const int* __restrict__ dst0,
    const int* __restrict__ src1, const int* __restrict__ dst1)
{
    int e = blockIdx.x * 256 + threadIdx.x;
    if (e >= NEDGE_T) return;
    int s, seg;
    if (e < N_EDGESC) { s = src0[e]; seg = dst0[e]; }
    else { int e2 = e - N_EDGESC; s = src1[e2]; seg = N_NODESC + dst1[e2]; }
    int pos = atomicAdd(&g_cursor[seg], 1);
    g_ssorted[pos] = s;
}

// ---------------- aggregate: warp per node, both etypes, write rst once ------
__global__ void __launch_bounds__(256) aggregate_kernel(const float* __restrict__ feat)
{
    int warp = (blockIdx.x * 256 + threadIdx.x) >> 5;
    int lane = threadIdx.x & 31;
    if (warp >= N_NODESC) return;

    float4 sum0 = make_float4(0.f, 0.f, 0.f, 0.f);
    float4 sum1 = make_float4(0.f, 0.f, 0.f, 0.f);
    int b0 = g_start[warp],            d0 = g_deg[warp];
    int b1 = g_start[N_NODESC + warp], d1 = g_deg[N_NODESC + warp];

    #pragma unroll 1
    for (int e = 0; e + 4 <= d0; e += 4) {
        int i0 = g_ssorted[b0 + e], i1 = g_ssorted[b0 + e + 1];
        int i2 = g_ssorted[b0 + e + 2], i3 = g_ssorted[b0 + e + 3];
        float4 v0 = *(const float4*)(feat + (size_t)i0 * HIDDENC + lane * 4);
        float4 v1 = *(const float4*)(feat + (size_t)i1 * HIDDENC + lane * 4);
        float4 v2 = *(const float4*)(feat + (size_t)i2 * HIDDENC + lane * 4);
        float4 v3 = *(const float4*)(feat + (size_t)i3 * HIDDENC + lane * 4);
        sum0.x += v0.x + v1.x + v2.x + v3.x;
        sum0.y += v0.y + v1.y + v2.y + v3.y;
        sum0.z += v0.z + v1.z + v2.z + v3.z;
        sum0.w += v0.w + v1.w + v2.w + v3.w;
    }
    for (int e = d0 & ~3; e < d0; e++) {
        int i0 = g_ssorted[b0 + e];
        float4 v = *(const float4*)(feat + (size_t)i0 * HIDDENC + lane * 4);
        sum0.x += v.x; sum0.y += v.y; sum0.z += v.z; sum0.w += v.w;
    }
    #pragma unroll 1
    for (int e = 0; e + 4 <= d1; e += 4) {
        int i0 = g_ssorted[b1 + e], i1 = g_ssorted[b1 + e + 1];
        int i2 = g_ssorted[b1 + e + 2], i3 = g_ssorted[b1 + e + 3];
        float4 v0 = *(const float4*)(feat + (size_t)i0 * HIDDENC + lane * 4);
        float4 v1 = *(const float4*)(feat + (size_t)i1 * HIDDENC + lane * 4);
        float4 v2 = *(const float4*)(feat + (size_t)i2 * HIDDENC + lane * 4);
        float4 v3 = *(const float4*)(feat + (size_t)i3 * HIDDENC + lane * 4);
        sum1.x += v0.x + v1.x + v2.x + v3.x;
        sum1.y += v0.y + v1.y + v2.y + v3.y;
        sum1.z += v0.z + v1.z + v2.z + v3.z;
        sum1.w += v0.w + v1.w + v2.w + v3.w;
    }
    for (int e = d1 & ~3; e < d1; e++) {
        int i0 = g_ssorted[b1 + e];
        float4 v = *(const float4*)(feat + (size_t)i0 * HIDDENC + lane * 4);
        sum1.x += v.x; sum1.y += v.y; sum1.z += v.z; sum1.w += v.w;
    }

    float i0f = 1.0f / (float)max(d0, 1);
    float i1f = 1.0f / (float)max(d1, 1);
    float has = (d0 > 0 ? 1.0f : 0.0f) + (d1 > 0 ? 1.0f : 0.0f);
    float ia = 1.0f / fmaxf(has, 1.0f);
    float4 r;
    r.x = (sum0.x * i0f + sum1.x * i1f) * ia;
    r.y = (sum0.y * i0f + sum1.y * i1f) * ia;
    r.z = (sum0.z * i0f + sum1.z * i1f) * ia;
    r.w = (sum0.w * i0f + sum1.w * i1f) * ia;
    *(float4*)(g_rst + (size_t)warp * HIDDENC + lane * 4) = r;
}

// ---------------- gemm1: gates = bias + feat @ Wih^T (K=128) -----------------
#define NPB   64
#define XPAD  68

struct Smem1 {
    float Ws[128 * GATESC];   // 128KB
    float XT[128 * XPAD];     // k-major feat tile
    float bias[GATESC];
};

__global__ void __launch_bounds__(512, 1) gemm1_kernel(const float* __restrict__ feat)
{
    extern __shared__ float smraw[];
    Smem1* sm = (Smem1*)smraw;
    const int t  = threadIdx.x;
    const int n0 = blockIdx.x * NPB;

    if (t < GATESC) sm->bias[t] = g_bias[t];

    // stage XT (feat, k-major)
    #pragma unroll
    for (int i = 0; i < (NPB * HIDDENC) / 512; i++) {    // 16 iters
        int idx = t + i * 512;
        int nn = idx >> 7, c = idx & 127;
        int n = n0 + nn;
        sm->XT[c * XPAD + nn] = (n < N_NODESC) ? feat[(size_t)n * HIDDENC + c] : 0.0f;
    }
    // stage Wih^T
    #pragma unroll
    for (int i = 0; i < (128 * GATESC) / (512 * 4); i++) {   // 16 iters
        int idx = t + i * 512;
        ((float4*)sm->Ws)[idx] = ((const float4*)g_WT)[idx];
    }
    __syncthreads();

    const int tx = t & 63;    // gates tx*4..+3
    const int ty = t >> 6;    // nodes ty*8..+7
    float acc[4][8];
    {
        float4 bv = *(float4*)&sm->bias[tx * 4];
        #pragma unroll
        for (int j = 0; j < 8; j++) { acc[0][j] = bv.x; acc[1][j] = bv.y; acc[2][j] = bv.z; acc[3][j] = bv.w; }
    }
    const float* Xb = &sm->XT[ty * 8];

    #pragma unroll 4
    for (int k = 0; k < HIDDENC; k++) {
        float4 w = *(float4*)&sm->Ws[k * GATESC + tx * 4];
        const float* xr = Xb + k * XPAD;
        float xv[8];
        *(float4*)&xv[0] = *(const float4*)(xr);
        *(float4*)&xv[4] = *(const float4*)(xr + 4);
        #pragma unroll
        for (int j = 0; j < 8; j++) {
            acc[0][j] = fmaf(w.x, xv[j], acc[0][j]);
            acc[1][j] = fmaf(w.y, xv[j], acc[1][j]);
            acc[2][j] = fmaf(w.z, xv[j], acc[2][j]);
            acc[3][j] = fmaf(w.w, xv[j], acc[3][j]);
        }
    }
    #pragma unroll
    for (int j = 0; j < 8; j++) {
        int n = n0 + ty * 8 + j;
        if (n < N_NODESC)
            *(float4*)&g_gates[(size_t)n * GATESC + tx * 4] =
                make_float4(acc[0][j], acc[1][j], acc[2][j], acc[3][j]);
    }
}

// ---------------- gemm2: gates += G@Whh^T (K=64), LSTM epilogue --------------
struct Smem2 {
    float Ws[MSGC * GATESC];  // 64KB: Whh^T, then reused as node-major gates
    float XT[MSGC * XPAD];    // k-major G tile
    float R[NPB * MSGC];
};

__device__ __forceinline__ float sigf(float x) { return 1.0f / (1.0f + __expf(-x)); }

__global__ void __launch_bounds__(512, 2) gemm2_kernel(float* __restrict__ out)
{
    extern __shared__ float smraw[];
    Smem2* sm = (Smem2*)smraw;
    const int t  = threadIdx.x;
    const int n0 = blockIdx.x * NPB;

    // stage G (rst cols 0..63) and R (rst cols 64..127)
    #pragma unroll
    for (int i = 0; i < (NPB * HIDDENC) / 512; i++) {    // 16 iters
        int idx = t + i * 512;
        int nn = idx >> 7, c = idx & 127;
        int n = n0 + nn;
        float v = (n < N_NODESC) ? g_rst[(size_t)n * HIDDENC + c] : 0.0f;
        if (c < MSGC) sm->XT[c * XPAD + nn] = v;
        else          sm->R[nn * MSGC + (c - MSGC)] = v;
    }
    // stage Whh^T (g_WT rows 128..191)
    #pragma unroll
    for (int i = 0; i < (MSGC * GATESC) / (512 * 4); i++) {   // 8 iters
        int idx = t + i * 512;
        ((float4*)sm->Ws)[idx] = ((const float4*)g_WT)[(128 * GATESC) / 4 + idx];
    }
    __syncthreads();

    const int tx = t & 63;
    const int ty = t >> 6;
    float acc[4][8];
    #pragma unroll
    for (int j = 0; j < 8; j++) {
        int n = n0 + ty * 8 + j;
        float4 gv = (n < N_NODESC) ? *(const float4*)&g_gates[(size_t)n * GATESC + tx * 4]
                                   : make_float4(0.f, 0.f, 0.f, 0.f);
        acc[0][j] = gv.x; acc[1][j] = gv.y; acc[2][j] = gv.z; acc[3][j] = gv.w;
    }
    const float* Xb = &sm->XT[ty * 8];

    #pragma unroll 4
    for (int k = 0; k < MSGC; k++) {
        float4 w = *(float4*)&sm->Ws[k * GATESC + tx * 4];
        const float* xr = Xb + k * XPAD;
        float xv[8];
        *(float4*)&xv[0] = *(const float4*)(xr);
        *(float4*)&xv[4] = *(const float4*)(xr + 4);
        #pragma unroll
        for (int j = 0; j < 8; j++) {
            acc[0][j] = fmaf(w.x, xv[j], acc[0][j]);
            acc[1][j] = fmaf(w.y, xv[j], acc[1][j]);
            acc[2][j] = fmaf(w.z, xv[j], acc[2][j]);
            acc[3][j] = fmaf(w.w, xv[j], acc[3][j]);
        }
    }
    __syncthreads();   // done reading Ws

    // write gates node-major into Ws region
    #pragma unroll
    for (int j = 0; j < 8; j++) {
        int n = ty * 8 + j;
        *(float4*)&sm->Ws[n * GATESC + tx * 4] =
            make_float4(acc[0][j], acc[1][j], acc[2][j], acc[3][j]);
    }
    __syncthreads();

    // LSTM epilogue: 8 threads per node, 8 cols each
    {
        int n  = t >> 3;
        int j0 = (t & 7) * 8;
        if (n0 + n < N_NODESC) {
            float h[8], c[8];
            const float* gs = &sm->Ws[n * GATESC];
            #pragma unroll
            for (int jj = 0; jj < 8; jj++) {
                int j = j0 + jj;
                float gi = gs[j];
                float gf = gs[MSGC + j];
                float gg = gs[2 * MSGC + j];
                float go = gs[3 * MSGC + j];
                float Rv = sm->R[n * MSGC + j];
                float cc = sigf(gf) * Rv + sigf(gi) * tanhf(gg);
                c[jj] = cc;
                h[jj] = sigf(go) * tanhf(cc);
            }
            float* orow = out + (size_t)(n0 + n) * HIDDENC;
            *(float4*)&orow[j0]            = *(float4*)&h[0];
            *(float4*)&orow[j0 + 4]        = *(float4*)&h[4];
            *(float4*)&orow[MSGC + j0]     = *(float4*)&c[0];
            *(float4*)&orow[MSGC + j0 + 4] = *(float4*)&c[4];
        }
    }
}

// ---------------- launch ----------------
static cudaStream_t g_s2;
static cudaEvent_t  g_evFork, g_evJoin;
static bool         g_init = false;

extern "C" void kernel_launch(void* const* d_in, const int* in_sizes, int n_in,
                              void* d_out, int out_size)
{
    const float* feat = (const float*)d_in[0];
    const int*   src0 = (const int*)d_in[1];
    const int*   dst0 = (const int*)d_in[2];
    const int*   src1 = (const int*)d_in[3];
    const int*   dst1 = (const int*)d_in[4];
    const float* W_ih = (const float*)d_in[5];
    const float* W_hh = (const float*)d_in[6];
    const float* b_ih = (const float*)d_in[7];
    const float* b_hh = (const float*)d_in[8];
    float* out = (float*)d_out;

    if (!g_init) {
        cudaStreamCreateWithFlags(&g_s2, cudaStreamNonBlocking);
        cudaEventCreateWithFlags(&g_evFork, cudaEventDisableTiming);
        cudaEventCreateWithFlags(&g_evJoin, cudaEventDisableTiming);
        cudaFuncSetAttribute(gemm1_kernel, cudaFuncAttributeMaxDynamicSharedMemorySize,
                             (int)sizeof(Smem1));
        cudaFuncSetAttribute(gemm2_kernel, cudaFuncAttributeMaxDynamicSharedMemorySize,
                             (int)sizeof(Smem2));
        g_init = true;
    }

    void* degp = nullptr;  cudaGetSymbolAddress(&degp, g_deg);
    void* bsump = nullptr; cudaGetSymbolAddress(&bsump, g_bsum);

    // ---- stream 0: CSR build + aggregate ----
    cudaMemsetAsync(degp, 0, NSEG * sizeof(int), 0);
    cudaMemsetAsync(bsump, 0, SCAN_NB * sizeof(int), 0);

    // fork: prep + gemm1 run on g_s2 concurrently with the CSR chain
    cudaEventRecord(g_evFork, 0);
    cudaStreamWaitEvent(g_s2, g_evFork, 0);
    prep_kernel<<<192, GATESC, 0, g_s2>>>(W_ih, W_hh, b_ih, b_hh);
    {
        int nblocks = (N_NODESC + NPB - 1) / NPB;
        gemm1_kernel<<<nblocks, 512, (int)sizeof(Smem1), g_s2>>>(feat);
    }

    count_kernel<<<(NEDGE_T + 255) / 256, 256>>>(dst0, dst1);
    scanA_kernel<<<SCAN_NB, SCAN_BS>>>();
    scanB_kernel<<<1, 32>>>();
    scanC_kernel<<<SCAN_NB, SCAN_BS>>>();
    fill_kernel<<<(NEDGE_T + 255) / 256, 256>>>(src0, dst0, src1, dst1);
    aggregate_kernel<<<(N_NODESC * 32 + 255) / 256, 256>>>(feat);

    // join
    cudaEventRecord(g_evJoin, g_s2);
    cudaStreamWaitEvent(0, g_evJoin, 0);

    {
        int nblocks = (N_NODESC + NPB - 1) / NPB;
        gemm2_kernel<<<nblocks, 512, (int)sizeof(Smem2)>>>(out);
    }
}

// round 3
// speedup vs baseline: 1.5120x; 1.0271x over previous
#include <cuda_runtime.h>
#include <math.h>
#include <stdint.h>

#define N_NODESC 50000
#define N_EDGESC 800000
#define HIDDENC  128
#define MSGC     64
#define GATESC   256
#define NSEG     (2 * N_NODESC)
#define NEDGE_T  (2 * N_EDGESC)
#define SCAN_BS  512
#define SCAN_NB  ((NSEG + SCAN_BS - 1) / SCAN_BS)   // 196

// ---------------- device scratch ----------------
__device__ int   g_deg[NSEG];
__device__ int   g_start[NSEG];
__device__ int   g_cursor[NSEG];
__device__ int   g_bsum[SCAN_NB];
__device__ int   g_ssorted[NEDGE_T];
__device__ float g_rst[(size_t)N_NODESC * HIDDENC];
__device__ float g_gates[(size_t)N_NODESC * GATESC];    // gemm1: bias + feat@Wih^T
__device__ float g_gates2[(size_t)N_NODESC * GATESC];   // aggregate-fused: G@Whh^T
__device__ float g_WT[192 * GATESC];   // [k][r]: rows 0..127 Wih^T, 128..191 Whh^T
__device__ float g_bias[GATESC];

// ---------------- prep ----------------
__global__ void prep_kernel(const float* __restrict__ W_ih, const float* __restrict__ W_hh,
                            const float* __restrict__ b_ih, const float* __restrict__ b_hh)
{
    int r = threadIdx.x;
    int k = blockIdx.x;
    float v;
    if (k < HIDDENC) v = W_ih[r * HIDDENC + k];
    else             v = W_hh[r * MSGC + (k - HIDDENC)];
    g_WT[k * GATESC + r] = v;
    if (k == 0) g_bias[r] = b_ih[r] + b_hh[r];
}

// ---------------- CSR build ----------------
__global__ void __launch_bounds__(256) count_kernel(
    const int* __restrict__ dst0, const int* __restrict__ dst1)
{
    int e = blockIdx.x * 256 + threadIdx.x;
    if (e >= NEDGE_T) return;
    if (e < N_EDGESC) atomicAdd(&g_deg[dst0[e]], 1);
    else              atomicAdd(&g_deg[N_NODESC + dst1[e - N_EDGESC]], 1);
}

__global__ void __launch_bounds__(SCAN_BS) scanA_kernel()
{
    __shared__ int s[SCAN_BS];
    int tid = threadIdx.x;
    int i = blockIdx.x * SCAN_BS + tid;
    int v = (i < NSEG) ? g_deg[i] : 0;
    s[tid] = v;
    __syncthreads();
    #pragma unroll
    for (int off = 1; off < SCAN_BS; off <<= 1) {
        int x = (tid >= off) ? s[tid - off] : 0;
        __syncthreads();
        s[tid] += x;
        __syncthreads();
    }
    if (i < NSEG) g_start[i] = s[tid] - v;
    if (tid == SCAN_BS - 1) g_bsum[blockIdx.x] = s[tid];
}

// one-warp shfl scan over SCAN_NB block sums
__global__ void scanB_kernel()
{
    const int PER = (SCAN_NB + 31) / 32;   // 7
    int tid = threadIdx.x;
    int base = tid * PER;
    int vals[PER];
    int tot = 0;
    #pragma unroll
    for (int i = 0; i < PER; i++) {
        int idx = base + i;
        int t = (idx < SCAN_NB) ? g_bsum[idx] : 0;
        vals[i] = tot;          // exclusive within thread
        tot += t;
    }
    int x = tot;
    #pragma unroll
    for (int off = 1; off < 32; off <<= 1) {
        int y = __shfl_up_sync(0xFFFFFFFFu, x, off);
        if (tid >= off) x += y;
    }
    int excl = x - tot;
    #pragma unroll
    for (int i = 0; i < PER; i++) {
        int idx = base + i;
        if (idx < SCAN_NB) g_bsum[idx] = excl + vals[i];
    }
}

__global__ void __launch_bounds__(SCAN_BS) scanC_kernel()
{
    int i = blockIdx.x * SCAN_BS + threadIdx.x;
    if (i < NSEG) {
        int v = g_start[i] + g_bsum[blockIdx.x];
        g_start[i] = v;
        g_cursor[i] = v;
    }
}

__global__ void __launch_bounds__(256) fill_kernel(
    const int* __restrict__ src0, const int* __restrict__ dst0,
    const int* __restrict__ src1, const int* __restrict__ dst1)
{
    int e = blockIdx.x * 256 + threadIdx.x;
    if (e >= NEDGE_T) return;
    int s, seg;
    if (e < N_EDGESC) { s = src0[e]; seg = dst0[e]; }
    else { int e2 = e - N_EDGESC; s = src1[e2]; seg = N_NODESC + dst1[e2]; }
    int pos = atomicAdd(&g_cursor[seg], 1);
    g_ssorted[pos] = s;
}

// ---------------- fused aggregate + Whh GEMM ----------------
// block: 512 threads (16 warps), 64 nodes. Warp w aggregates nodes w*4..w*4+3,
// writes rst, stages G k-major in smem; then block GEMM G@Whh^T -> g_gates2.
#define AGG_NPB  64
#define GXPAD    67

struct SmemA {
    float Ws[MSGC * GATESC];   // 64KB Whh^T
    float sX[MSGC * GXPAD];    // k-major G tile [k][node]
};

__global__ void __launch_bounds__(512, 2) aggregate_kernel(const float* __restrict__ feat)
{
    extern __shared__ float smraw[];
    SmemA* sm = (SmemA*)smraw;
    const int t    = threadIdx.x;
    const int wid  = t >> 5;
    const int lane = t & 31;
    const int n0   = blockIdx.x * AGG_NPB;

    // stage Whh^T (g_WT rows 128..191)
    #pragma unroll
    for (int i = 0; i < (MSGC * GATESC) / (512 * 4); i++) {   // 8 iters
        int idx = t + i * 512;
        ((float4*)sm->Ws)[idx] = ((const float4*)g_WT)[(128 * GATESC) / 4 + idx];
    }

    // aggregation: warp per node, 4 nodes per warp
    #pragma unroll 1
    for (int i = 0; i < 4; i++) {
        int nn = wid * 4 + i;
        int n  = n0 + nn;
        if (n >= N_NODESC) break;

        float4 sum0 = make_float4(0.f, 0.f, 0.f, 0.f);
        float4 sum1 = make_float4(0.f, 0.f, 0.f, 0.f);
        int b0 = g_start[n],            d0 = g_deg[n];
        int b1 = g_start[N_NODESC + n], d1 = g_deg[N_NODESC + n];

        #pragma unroll 1
        for (int e = 0; e + 4 <= d0; e += 4) {
            int i0 = g_ssorted[b0 + e],     i1 = g_ssorted[b0 + e + 1];
            int i2 = g_ssorted[b0 + e + 2], i3 = g_ssorted[b0 + e + 3];
            float4 v0 = *(const float4*)(feat + (size_t)i0 * HIDDENC + lane * 4);
            float4 v1 = *(const float4*)(feat + (size_t)i1 * HIDDENC + lane * 4);
            float4 v2 = *(const float4*)(feat + (size_t)i2 * HIDDENC + lane * 4);
            float4 v3 = *(const float4*)(feat + (size_t)i3 * HIDDENC + lane * 4);
            sum0.x += v0.x + v1.x + v2.x + v3.x;
            sum0.y += v0.y + v1.y + v2.y + v3.y;
            sum0.z += v0.z + v1.z + v2.z + v3.z;
            sum0.w += v0.w + v1.w + v2.w + v3.w;
        }
        for (int e = d0 & ~3; e < d0; e++) {
            int i0 = g_ssorted[b0 + e];
            float4 v = *(const float4*)(feat + (size_t)i0 * HIDDENC + lane * 4);
            sum0.x += v.x; sum0.y += v.y; sum0.z += v.z; sum0.w += v.w;
        }
        #pragma unroll 1
        for (int e = 0; e + 4 <= d1; e += 4) {
            int i0 = g_ssorted[b1 + e],     i1 = g_ssorted[b1 + e + 1];
            int i2 = g_ssorted[b1 + e + 2], i3 = g_ssorted[b1 + e + 3];
            float4 v0 = *(const float4*)(feat + (size_t)i0 * HIDDENC + lane * 4);
            float4 v1 = *(const float4*)(feat + (size_t)i1 * HIDDENC + lane * 4);
            float4 v2 = *(const float4*)(feat + (size_t)i2 * HIDDENC + lane * 4);
            float4 v3 = *(const float4*)(feat + (size_t)i3 * HIDDENC + lane * 4);
            sum1.x += v0.x + v1.x + v2.x + v3.x;
            sum1.y += v0.y + v1.y + v2.y + v3.y;
            sum1.z += v0.z + v1.z + v2.z + v3.z;
            sum1.w += v0.w + v1.w + v2.w + v3.w;
        }
        for (int e = d1 & ~3; e < d1; e++) {
            int i0 = g_ssorted[b1 + e];
            float4 v = *(const float4*)(feat + (size_t)i0 * HIDDENC + lane * 4);
            sum1.x += v.x; sum1.y += v.y; sum1.z += v.z; sum1.w += v.w;
        }

        float i0f = 1.0f / (float)max(d0, 1);
        float i1f = 1.0f / (float)max(d1, 1);
        float has = (d0 > 0 ? 1.0f : 0.0f) + (d1 > 0 ? 1.0f : 0.0f);
        float ia = 1.0f / fmaxf(has, 1.0f);
        float4 r;
        r.x = (sum0.x * i0f + sum1.x * i1f) * ia;
        r.y = (sum0.y * i0f + sum1.y * i1f) * ia;
        r.z = (sum0.z * i0f + sum1.z * i1f) * ia;
        r.w = (sum0.w * i0f + sum1.w * i1f) * ia;
        *(float4*)(g_rst + (size_t)n * HIDDENC + lane * 4) = r;

        // G = cols 0..63 live in lanes 0..15; stage k-major
        if (lane < 16) {
            sm->sX[(4 * lane + 0) * GXPAD + nn] = r.x;
            sm->sX[(4 * lane + 1) * GXPAD + nn] = r.y;
            sm->sX[(4 * lane + 2) * GXPAD + nn] = r.z;
            sm->sX[(4 * lane + 3) * GXPAD + nn] = r.w;
        }
    }
    __syncthreads();

    // block GEMM: [64 nodes x 64 K] @ Whh^T[64K x 256 gates]
    const int tx = t & 63;    // gate quad
    const int ty = t >> 6;    // node group: nodes ty*8..+7
    float acc[4][8];
    #pragma unroll
    for (int j = 0; j < 8; j++) { acc[0][j] = 0.f; acc[1][j] = 0.f; acc[2][j] = 0.f; acc[3][j] = 0.f; }

    #pragma unroll 4
    for (int k = 0; k < MSGC; k++) {
        float4 w = *(float4*)&sm->Ws[k * GATESC + tx * 4];
        const float* xr = &sm->sX[k * GXPAD + ty * 8];
        #pragma unroll
        for (int j = 0; j < 8; j++) {
            float xv = xr[j];
            acc[0][j] = fmaf(w.x, xv, acc[0][j]);
            acc[1][j] = fmaf(w.y, xv, acc[1][j]);
            acc[2][j] = fmaf(w.z, xv, acc[2][j]);
            acc[3][j] = fmaf(w.w, xv, acc[3][j]);
        }
    }
    #pragma unroll
    for (int j = 0; j < 8; j++) {
        int n = n0 + ty * 8 + j;
        if (n < N_NODESC)
            *(float4*)&g_gates2[(size_t)n * GATESC + tx * 4] =
                make_float4(acc[0][j], acc[1][j], acc[2][j], acc[3][j]);
    }
}

// ---------------- gemm1: gates = bias + feat @ Wih^T (K=128) -----------------
#define NPB   64
#define XPAD  68

struct Smem1 {
    float Ws[128 * GATESC];
    float XT[128 * XPAD];
    float bias[GATESC];
};

__global__ void __launch_bounds__(512, 1) gemm1_kernel(const float* __restrict__ feat)
{
    extern __shared__ float smraw[];
    Smem1* sm = (Smem1*)smraw;
    const int t  = threadIdx.x;
    const int n0 = blockIdx.x * NPB;

    if (t < GATESC) sm->bias[t] = g_bias[t];

    #pragma unroll
    for (int i = 0; i < (NPB * HIDDENC) / 512; i++) {
        int idx = t + i * 512;
        int nn = idx >> 7, c = idx & 127;
        int n = n0 + nn;
        sm->XT[c * XPAD + nn] = (n < N_NODESC) ? feat[(size_t)n * HIDDENC + c] : 0.0f;
    }
    #pragma unroll
    for (int i = 0; i < (128 * GATESC) / (512 * 4); i++) {
        int idx = t + i * 512;
        ((float4*)sm->Ws)[idx] = ((const float4*)g_WT)[idx];
    }
    __syncthreads();

    const int tx = t & 63;
    const int ty = t >> 6;
    float acc[4][8];
    {
        float4 bv = *(float4*)&sm->bias[tx * 4];
        #pragma unroll
        for (int j = 0; j < 8; j++) { acc[0][j] = bv.x; acc[1][j] = bv.y; acc[2][j] = bv.z; acc[3][j] = bv.w; }
    }
    const float* Xb = &sm->XT[ty * 8];

    #pragma unroll 4
    for (int k = 0; k < HIDDENC; k++) {
        float4 w = *(float4*)&sm->Ws[k * GATESC + tx * 4];
        const float* xr = Xb + k * XPAD;
        float xv[8];
        *(float4*)&xv[0] = *(const float4*)(xr);
        *(float4*)&xv[4] = *(const float4*)(xr + 4);
        #pragma unroll
        for (int j = 0; j < 8; j++) {
            acc[0][j] = fmaf(w.x, xv[j], acc[0][j]);
            acc[1][j] = fmaf(w.y, xv[j], acc[1][j]);
            acc[2][j] = fmaf(w.z, xv[j], acc[2][j]);
            acc[3][j] = fmaf(w.w, xv[j], acc[3][j]);
        }
    }
    #pragma unroll
    for (int j = 0; j < 8; j++) {
        int n = n0 + ty * 8 + j;
        if (n < N_NODESC)
            *(float4*)&g_gates[(size_t)n * GATESC + tx * 4] =
                make_float4(acc[0][j], acc[1][j], acc[2][j], acc[3][j]);
    }
}

// ---------------- elementwise LSTM epilogue ----------------
__device__ __forceinline__ float sigf(float x) { return 1.0f / (1.0f + __expf(-x)); }

__global__ void __launch_bounds__(256) lstm_ep_kernel(float* __restrict__ out)
{
    int warp = (blockIdx.x * 256 + threadIdx.x) >> 5;
    int lane = threadIdx.x & 31;
    if (warp >= N_NODESC) return;
    const float* g1 = g_gates  + (size_t)warp * GATESC;
    const float* g2 = g_gates2 + (size_t)warp * GATESC;
    const float* R  = g_rst    + (size_t)warp * HIDDENC + MSGC;
    float* orow     = out      + (size_t)warp * HIDDENC;
    #pragma unroll
    for (int h = 0; h < 2; h++) {
        int j = lane + h * 32;
        float gi = g1[j]            + g2[j];
        float gf = g1[MSGC + j]     + g2[MSGC + j];
        float gg = g1[2 * MSGC + j] + g2[2 * MSGC + j];
        float go = g1[3 * MSGC + j] + g2[3 * MSGC + j];
        float Rv = R[j];
        float cc = sigf(gf) * Rv + sigf(gi) * tanhf(gg);
        orow[j]        = sigf(go) * tanhf(cc);
        orow[MSGC + j] = cc;
    }
}

// ---------------- launch ----------------
static cudaStream_t g_s2;
static cudaEvent_t  g_evFork, g_evPrep, g_evJoin;
static bool         g_init = false;

extern "C" void kernel_launch(void* const* d_in, const int* in_sizes, int n_in,
                              void* d_out, int out_size)
{
    const float* feat = (const float*)d_in[0];
    const int*   src0 = (const int*)d_in[1];
    const int*   dst0 = (const int*)d_in[2];
    const int*   src1 = (const int*)d_in[3];
    const int*   dst1 = (const int*)d_in[4];
    const float* W_ih = (const float*)d_in[5];
    const float* W_hh = (const float*)d_in[6];
    const float* b_ih = (const float*)d_in[7];
    const float* b_hh = (const float*)d_in[8];
    float* out = (float*)d_out;

    if (!g_init) {
        cudaStreamCreateWithFlags(&g_s2, cudaStreamNonBlocking);
        cudaEventCreateWithFlags(&g_evFork, cudaEventDisableTiming);
        cudaEventCreateWithFlags(&g_evPrep, cudaEventDisableTiming);
        cudaEventCreateWithFlags(&g_evJoin, cudaEventDisableTiming);
        cudaFuncSetAttribute(gemm1_kernel, cudaFuncAttributeMaxDynamicSharedMemorySize,
                             (int)sizeof(Smem1));
        cudaFuncSetAttribute(aggregate_kernel, cudaFuncAttributeMaxDynamicSharedMemorySize,
                             (int)sizeof(SmemA));
        g_init = true;
    }

    void* degp = nullptr;  cudaGetSymbolAddress(&degp, g_deg);

    cudaMemsetAsync(degp, 0, NSEG * sizeof(int), 0);

    // fork: prep + gemm1 on g_s2
    cudaEventRecord(g_evFork, 0);
    cudaStreamWaitEvent(g_s2, g_evFork, 0);
    prep_kernel<<<192, GATESC, 0, g_s2>>>(W_ih, W_hh, b_ih, b_hh);
    cudaEventRecord(g_evPrep, g_s2);
    {
        int nblocks = (N_NODESC + NPB - 1) / NPB;
        gemm1_kernel<<<nblocks, 512, (int)sizeof(Smem1), g_s2>>>(feat);
    }
    cudaEventRecord(g_evJoin, g_s2);

    // stream 0: CSR build
    count_kernel<<<(NEDGE_T + 255) / 256, 256>>>(dst0, dst1);
    scanA_kernel<<<SCAN_NB, SCAN_BS>>>();
    scanB_kernel<<<1, 32>>>();
    scanC_kernel<<<SCAN_NB, SCAN_BS>>>();
    fill_kernel<<<(NEDGE_T + 255) / 256, 256>>>(src0, dst0, src1, dst1);

    // aggregate needs g_WT (prep)
    cudaStreamWaitEvent(0, g_evPrep, 0);
    {
        int nblocks = (N_NODESC + AGG_NPB - 1) / AGG_NPB;
        aggregate_kernel<<<nblocks, 512, (int)sizeof(SmemA)>>>(feat);
    }

    // epilogue needs gemm1
    cudaStreamWaitEvent(0, g_evJoin, 0);
    {
        int nblocks = (N_NODESC * 32 + 255) / 256;
        lstm_ep_kernel<<<nblocks, 256>>>(out);
    }
}

// round 5
// speedup vs baseline: 2.1428x; 1.4172x over previous
#include <cuda_runtime.h>
#include <math.h>
#include <stdint.h>

#define N_NODESC 50000
#define N_EDGESC 800000
#define HIDDENC  128
#define MSGC     64
#define GATESC   256
#define NSEG     (2 * N_NODESC)
#define NEDGE_T  (2 * N_EDGESC)
#define SCAN_BS  512
#define SCAN_NB  ((NSEG + SCAN_BS - 1) / SCAN_BS)   // 196

// ---------------- device scratch ----------------
__device__ int      g_deg[NSEG];
__device__ int      g_start[NSEG];
__device__ int      g_cursor[NSEG];
__device__ int      g_bsum[SCAN_NB];
__device__ int      g_ssorted[NEDGE_T];
__device__ float    g_rst[(size_t)N_NODESC * HIDDENC];
__device__ float    g_gates[(size_t)N_NODESC * GATESC];   // gemm1: bias + feat@Wih^T
__device__ uint32_t g_WTt[192 * GATESC];  // tf32 [k][gate]: rows 0..127 Wih^T, 128..191 Whh^T
__device__ float    g_bias[GATESC];

__device__ __forceinline__ uint32_t f2tf(float f) {
    uint32_t u;
    asm("cvt.rna.tf32.f32 %0, %1;" : "=r"(u) : "f"(f));
    return u;
}

__device__ __forceinline__ void mma_tf32(float& d0, float& d1, float& d2, float& d3,
                                         uint32_t a0, uint32_t a1, uint32_t a2, uint32_t a3,
                                         uint32_t b0, uint32_t b1)
{
    asm volatile("mma.sync.aligned.m16n8k8.row.col.f32.tf32.tf32.f32 "
                 "{%0,%1,%2,%3}, {%4,%5,%6,%7}, {%8,%9}, {%0,%1,%2,%3};\n"
                 : "+f"(d0), "+f"(d1), "+f"(d2), "+f"(d3)
                 : "r"(a0), "r"(a1), "r"(a2), "r"(a3), "r"(b0), "r"(b1));
}

// ---------------- prep: transpose W -> tf32, combine bias ----------------
__global__ void prep_kernel(const float* __restrict__ W_ih, const float* __restrict__ W_hh,
                            const float* __restrict__ b_ih, const float* __restrict__ b_hh)
{
    int r = threadIdx.x;   // gate 0..255
    int k = blockIdx.x;    // 0..191
    float v;
    if (k < HIDDENC) v = W_ih[r * HIDDENC + k];
    else             v = W_hh[r * MSGC + (k - HIDDENC)];
    g_WTt[k * GATESC + r] = f2tf(v);
    if (k == 0) g_bias[r] = b_ih[r] + b_hh[r];
}

// ---------------- CSR build ----------------
__global__ void __launch_bounds__(256) count_kernel(
    const int* __restrict__ dst0, const int* __restrict__ dst1)
{
    int e = blockIdx.x * 256 + threadIdx.x;
    if (e >= NEDGE_T) return;
    if (e < N_EDGESC) atomicAdd(&g_deg[dst0[e]], 1);
    else              atomicAdd(&g_deg[N_NODESC + dst1[e - N_EDGESC]], 1);
}

__global__ void __launch_bounds__(SCAN_BS) scanA_kernel()
{
    __shared__ int s[SCAN_BS];
    int tid = threadIdx.x;
    int i = blockIdx.x * SCAN_BS + tid;
    int v = (i < NSEG) ? g_deg[i] : 0;
    s[tid] = v;
    __syncthreads();
    #pragma unroll
    for (int off = 1; off < SCAN_BS; off <<= 1) {
        int x = (tid >= off) ? s[tid - off] : 0;
        __syncthreads();
        s[tid] += x;
        __syncthreads();
    }
    if (i < NSEG) g_start[i] = s[tid] - v;
    if (tid == SCAN_BS - 1) g_bsum[blockIdx.x] = s[tid];
}

__global__ void scanB_kernel()
{
    const int PER = (SCAN_NB + 31) / 32;
    int tid = threadIdx.x;
    int base = tid * PER;
    int vals[PER];
    int tot = 0;
    #pragma unroll
    for (int i = 0; i < PER; i++) {
        int idx = base + i;
        int t = (idx < SCAN_NB) ? g_bsum[idx] : 0;
        vals[i] = tot;
        tot += t;
    }
    int x = tot;
    #pragma unroll
    for (int off = 1; off < 32; off <<= 1) {
        int y = __shfl_up_sync(0xFFFFFFFFu, x, off);
        if (tid >= off) x += y;
    }
    int excl = x - tot;
    #pragma unroll
    for (int i = 0; i < PER; i++) {
        int idx = base + i;
        if (idx < SCAN_NB) g_bsum[idx] = excl + vals[i];
    }
}

__global__ void __launch_bounds__(SCAN_BS) scanC_kernel()
{
    int i = blockIdx.x * SCAN_BS + threadIdx.x;
    if (i < NSEG) {
        int v = g_start[i] + g_bsum[blockIdx.x];
        g_start[i] = v;
        g_cursor[i] = v;
    }
}

__global__ void __launch_bounds__(256) fill_kernel(
    const int* __restrict__ src0, const int* __restrict__ dst0,
    const int* __restrict__ src1, const int* __restrict__ dst1)
{
    int e = blockIdx.x * 256 + threadIdx.x;
    if (e >= NEDGE_T) return;
    int s, seg;
    if (e < N_EDGESC) { s = src0[e]; seg = dst0[e]; }
    else { int e2 = e - N_EDGESC; s = src1[e2]; seg = N_NODESC + dst1[e2]; }
    int pos = atomicAdd(&g_cursor[seg], 1);
    g_ssorted[pos] = s;
}

// ---------------- aggregate: warp per node, write rst ----------------
__global__ void __launch_bounds__(256) aggregate_kernel(const float* __restrict__ feat)
{
    int warp = (blockIdx.x * 256 + threadIdx.x) >> 5;
    int lane = threadIdx.x & 31;
    if (warp >= N_NODESC) return;

    float4 sum0 = make_float4(0.f, 0.f, 0.f, 0.f);
    float4 sum1 = make_float4(0.f, 0.f, 0.f, 0.f);
    int b0 = g_start[warp],            d0 = g_deg[warp];
    int b1 = g_start[N_NODESC + warp], d1 = g_deg[N_NODESC + warp];

    #pragma unroll 1
    for (int e = 0; e + 4 <= d0; e += 4) {
        int i0 = g_ssorted[b0 + e],     i1 = g_ssorted[b0 + e + 1];
        int i2 = g_ssorted[b0 + e + 2], i3 = g_ssorted[b0 + e + 3];
        float4 v0 = *(const float4*)(feat + (size_t)i0 * HIDDENC + lane * 4);
        float4 v1 = *(const float4*)(feat + (size_t)i1 * HIDDENC + lane * 4);
        float4 v2 = *(const float4*)(feat + (size_t)i2 * HIDDENC + lane * 4);
        float4 v3 = *(const float4*)(feat + (size_t)i3 * HIDDENC + lane * 4);
        sum0.x += v0.x + v1.x + v2.x + v3.x;
        sum0.y += v0.y + v1.y + v2.y + v3.y;
        sum0.z += v0.z + v1.z + v2.z + v3.z;
        sum0.w += v0.w + v1.w + v2.w + v3.w;
    }
    for (int e = d0 & ~3; e < d0; e++) {
        int i0 = g_ssorted[b0 + e];
        float4 v = *(const float4*)(feat + (size_t)i0 * HIDDENC + lane * 4);
        sum0.x += v.x; sum0.y += v.y; sum0.z += v.z; sum0.w += v.w;
    }
    #pragma unroll 1
    for (int e = 0; e + 4 <= d1; e += 4) {
        int i0 = g_ssorted[b1 + e],     i1 = g_ssorted[b1 + e + 1];
        int i2 = g_ssorted[b1 + e + 2], i3 = g_ssorted[b1 + e + 3];
        float4 v0 = *(const float4*)(feat + (size_t)i0 * HIDDENC + lane * 4);
        float4 v1 = *(const float4*)(feat + (size_t)i1 * HIDDENC + lane * 4);
        float4 v2 = *(const float4*)(feat + (size_t)i2 * HIDDENC + lane * 4);
        float4 v3 = *(const float4*)(feat + (size_t)i3 * HIDDENC + lane * 4);
        sum1.x += v0.x + v1.x + v2.x + v3.x;
        sum1.y += v0.y + v1.y + v2.y + v3.y;
        sum1.z += v0.z + v1.z + v2.z + v3.z;
        sum1.w += v0.w + v1.w + v2.w + v3.w;
    }
    for (int e = d1 & ~3; e < d1; e++) {
        int i0 = g_ssorted[b1 + e];
        float4 v = *(const float4*)(feat + (size_t)i0 * HIDDENC + lane * 4);
        sum1.x += v.x; sum1.y += v.y; sum1.z += v.z; sum1.w += v.w;
    }

    float i0f = 1.0f / (float)max(d0, 1);
    float i1f = 1.0f / (float)max(d1, 1);
    float has = (d0 > 0 ? 1.0f : 0.0f) + (d1 > 0 ? 1.0f : 0.0f);
    float ia = 1.0f / fmaxf(has, 1.0f);
    float4 r;
    r.x = (sum0.x * i0f + sum1.x * i1f) * ia;
    r.y = (sum0.y * i0f + sum1.y * i1f) * ia;
    r.z = (sum0.z * i0f + sum1.z * i1f) * ia;
    r.w = (sum0.w * i0f + sum1.w * i1f) * ia;
    *(float4*)(g_rst + (size_t)warp * HIDDENC + lane * 4) = r;
}

// ---------------- gemm1 (tf32 MMA): gates = bias + feat @ Wih^T --------------
// block: 256 thr (8 warps), tile M=64 nodes x N=256 gates, K=128.
// warp grid 2(M) x 4(N): warp tile 32x64 = 2x8 m16n8 tiles.
#define G1_WPAD 264   // sW row stride (uint32)
#define G1_XPAD 132   // sX row stride
#define G1_SW_OFF   0
#define G1_SX_OFF   (128 * G1_WPAD)                 // uint32 units
#define G1_SB_OFF   (G1_SX_OFF + 64 * G1_XPAD)
#define G1_SMEM_BYTES ((G1_SB_OFF + 256) * 4)

__global__ void __launch_bounds__(256, 1) gemm1_kernel(const float* __restrict__ feat)
{
    extern __shared__ uint32_t smu[];
    uint32_t* sW = smu + G1_SW_OFF;     // [128][264] tf32
    uint32_t* sX = smu + G1_SX_OFF;     // [64][132] tf32 (node-major, k cols)
    float*    sB = (float*)(smu + G1_SB_OFF);

    const int t    = threadIdx.x;
    const int lane = t & 31;
    const int wid  = t >> 5;
    const int n0   = blockIdx.x * 64;

    if (t < 256) sB[t] = g_bias[t];

    // stage W: 128x256, uint4
    #pragma unroll
    for (int i = 0; i < 32; i++) {
        int idx = t + i * 256;          // 0..8191 uint4
        int kk = idx >> 6, n4 = idx & 63;
        uint4 v = ((const uint4*)g_WTt)[idx];
        *(uint4*)&sW[kk * G1_WPAD + n4 * 4] = v;
    }
    // stage X: 64x128 floats -> tf32
    #pragma unroll
    for (int i = 0; i < 8; i++) {
        int idx = t + i * 256;          // 0..2047 float4
        int nn = idx >> 5, c4 = idx & 31;
        int n = n0 + nn;
        float4 v = (n < N_NODESC) ? *(const float4*)(feat + (size_t)n * HIDDENC + c4 * 4)
                                  : make_float4(0.f, 0.f, 0.f, 0.f);
        uint32_t* d = &sX[nn * G1_XPAD + c4 * 4];
        d[0] = f2tf(v.x); d[1] = f2tf(v.y); d[2] = f2tf(v.z); d[3] = f2tf(v.w);
    }
    __syncthreads();

    const int wm = (wid >> 2) * 32;     // 0 / 32
    const int wn = (wid & 3) * 64;      // 0/64/128/192
    const int g  = lane >> 2;           // 0..7
    const int tq = lane & 3;            // 0..3

    float acc[2][8][4];
    #pragma unroll
    for (int mt = 0; mt < 2; mt++)
        #pragma unroll
        for (int nt = 0; nt < 8; nt++) {
            float b0 = sB[wn + nt * 8 + 2 * tq];
            float b1 = sB[wn + nt * 8 + 2 * tq + 1];
            acc[mt][nt][0] = b0; acc[mt][nt][1] = b1;
            acc[mt][nt][2] = b0; acc[mt][nt][3] = b1;
        }

    #pragma unroll 2
    for (int kk = 0; kk < 16; kk++) {
        int k0 = kk * 8;
        uint32_t a[2][4];
        #pragma unroll
        for (int mt = 0; mt < 2; mt++) {
            int mb = wm + mt * 16;
            a[mt][0] = sX[(mb + g) * G1_XPAD + k0 + tq];
            a[mt][1] = sX[(mb + g + 8) * G1_XPAD + k0 + tq];
            a[mt][2] = sX[(mb + g) * G1_XPAD + k0 + tq + 4];
            a[mt][3] = sX[(mb + g + 8) * G1_XPAD + k0 + tq + 4];
        }
        #pragma unroll
        for (int nt = 0; nt < 8; nt++) {
            int nb = wn + nt * 8 + g;
            uint32_t b0 = sW[(k0 + tq) * G1_WPAD + nb];
            uint32_t b1 = sW[(k0 + tq + 4) * G1_WPAD + nb];
            #pragma unroll
            for (int mt = 0; mt < 2; mt++)
                mma_tf32(acc[mt][nt][0], acc[mt][nt][1], acc[mt][nt][2], acc[mt][nt][3],
                         a[mt][0], a[mt][1], a[mt][2], a[mt][3], b0, b1);
        }
    }

    // write out
    #pragma unroll
    for (int mt = 0; mt < 2; mt++) {
        int node = n0 + wm + mt * 16 + g;
        #pragma unroll
        for (int nt = 0; nt < 8; nt++) {
            int col = wn + nt * 8 + 2 * tq;
            if (node < N_NODESC)
                *(float2*)&g_gates[(size_t)node * GATESC + col] =
                    make_float2(acc[mt][nt][0], acc[mt][nt][1]);
            if (node + 8 < N_NODESC)
                *(float2*)&g_gates[(size_t)(node + 8) * GATESC + col] =
                    make_float2(acc[mt][nt][2], acc[mt][nt][3]);
        }
    }
}

// ---------------- gemm2 (tf32 MMA) + LSTM epilogue ----------------
// gates_total = g_gates + G @ Whh^T ; then LSTM -> out
#define G2_WPAD 264
#define G2_XPAD 68
#define G2_GPAD 260
#define G2_SW_OFF 0
#define G2_SX_OFF (64 * G2_WPAD)                    // after sW (64 rows)
#define G2_SMEM_U32 (G2_SX_OFF + 64 * G2_XPAD)
#define G2_SMEM_BYTES (G2_SMEM_U32 * 4)
// sGates overlaps sW region after MMA: needs 64*260 = 16640 u32 <= 64*264

__device__ __forceinline__ float sigf(float x) { return 1.0f / (1.0f + __expf(-x)); }

__global__ void __launch_bounds__(256, 2) gemm2_kernel(float* __restrict__ out)
{
    extern __shared__ uint32_t smu[];
    uint32_t* sW = smu + G2_SW_OFF;   // [64][264] tf32 Whh^T
    uint32_t* sX = smu + G2_SX_OFF;   // [64][68]  tf32 G
    float*    sG = (float*)(smu + G2_SW_OFF);   // reused: [64][260] gates

    const int t    = threadIdx.x;
    const int lane = t & 31;
    const int wid  = t >> 5;
    const int n0   = blockIdx.x * 64;

    // stage Whh^T (g_WTt rows 128..191): 64x256, uint4
    #pragma unroll
    for (int i = 0; i < 16; i++) {
        int idx = t + i * 256;          // 0..4095 uint4
        int kk = idx >> 6, n4 = idx & 63;
        uint4 v = ((const uint4*)g_WTt)[(128 * GATESC) / 4 + idx];
        *(uint4*)&sW[kk * G2_WPAD + n4 * 4] = v;
    }
    // stage G: g_rst cols 0..63 -> tf32
    #pragma unroll
    for (int i = 0; i < 4; i++) {
        int idx = t + i * 256;          // 0..1023 float4
        int nn = idx >> 4, c4 = idx & 15;
        int n = n0 + nn;
        float4 v = (n < N_NODESC) ? *(const float4*)(g_rst + (size_t)n * HIDDENC + c4 * 4)
                                  : make_float4(0.f, 0.f, 0.f, 0.f);
        uint32_t* d = &sX[nn * G2_XPAD + c4 * 4];
        d[0] = f2tf(v.x); d[1] = f2tf(v.y); d[2] = f2tf(v.z); d[3] = f2tf(v.w);
    }
    __syncthreads();

    const int wm = (wid >> 2) * 32;
    const int wn = (wid & 3) * 64;
    const int g  = lane >> 2;
    const int tq = lane & 3;

    float acc[2][8][4];
    #pragma unroll
    for (int mt = 0; mt < 2; mt++) {
        int node = n0 + wm + mt * 16 + g;
        #pragma unroll
        for (int nt = 0; nt < 8; nt++) {
            int col = wn + nt * 8 + 2 * tq;
            float2 c01 = (node < N_NODESC) ? *(const float2*)&g_gates[(size_t)node * GATESC + col]
                                           : make_float2(0.f, 0.f);
            float2 c23 = (node + 8 < N_NODESC) ? *(const float2*)&g_gates[(size_t)(node + 8) * GATESC + col]
                                               : make_float2(0.f, 0.f);
            acc[mt][nt][0] = c01.x; acc[mt][nt][1] = c01.y;
            acc[mt][nt][2] = c23.x; acc[mt][nt][3] = c23.y;
        }
    }

    #pragma unroll
    for (int kk = 0; kk < 8; kk++) {
        int k0 = kk * 8;
        uint32_t a[2][4];
        #pragma unroll
        for (int mt = 0; mt < 2; mt++) {
            int mb = wm + mt * 16;
            a[mt][0] = sX[(mb + g) * G2_XPAD + k0 + tq];
            a[mt][1] = sX[(mb + g + 8) * G2_XPAD + k0 + tq];
            a[mt][2] = sX[(mb + g) * G2_XPAD + k0 + tq + 4];
            a[mt][3] = sX[(mb + g + 8) * G2_XPAD + k0 + tq + 4];
        }
        #pragma unroll
        for (int nt = 0; nt < 8; nt++) {
            int nb = wn + nt * 8 + g;
            uint32_t b0 = sW[(k0 + tq) * G2_WPAD + nb];
            uint32_t b1 = sW[(k0 + tq + 4) * G2_WPAD + nb];
            #pragma unroll
            for (int mt = 0; mt < 2; mt++)
                mma_tf32(acc[mt][nt][0], acc[mt][nt][1], acc[mt][nt][2], acc[mt][nt][3],
                         a[mt][0], a[mt][1], a[mt][2], a[mt][3], b0, b1);
        }
    }
    __syncthreads();   // done reading sW/sX -> reuse as sG

    #pragma unroll
    for (int mt = 0; mt < 2; mt++) {
        int nn = wm + mt * 16 + g;
        #pragma unroll
        for (int nt = 0; nt < 8; nt++) {
            int col = wn + nt * 8 + 2 * tq;
            *(float2*)&sG[nn * G2_GPAD + col]       = make_float2(acc[mt][nt][0], acc[mt][nt][1]);
            *(float2*)&sG[(nn + 8) * G2_GPAD + col] = make_float2(acc[mt][nt][2], acc[mt][nt][3]);
        }
    }
    __syncthreads();

    // LSTM epilogue: 4 threads per node, 16 cols each
    {
        int nn = t >> 2;
        int j0 = (t & 3) * 16;
        int n  = n0 + nn;
        if (n < N_NODESC) {
            const float* gs = &sG[nn * G2_GPAD];
            const float* R  = g_rst + (size_t)n * HIDDENC + MSGC;
            float h[16], c[16];
            #pragma unroll
            for (int jj = 0; jj < 16; jj++) {
                int j = j0 + jj;
                float gi = gs[j];
                float gf = gs[MSGC + j];
                float gg = gs[2 * MSGC + j];
                float go = gs[3 * MSGC + j];
                float cc = sigf(gf) * R[j] + sigf(gi) * tanhf(gg);
                c[jj] = cc;
                h[jj] = sigf(go) * tanhf(cc);
            }
            float* orow = out + (size_t)n * HIDDENC;
            #pragma unroll
            for (int q = 0; q < 4; q++) {
                *(float4*)&orow[j0 + q * 4]        = *(float4*)&h[q * 4];
                *(float4*)&orow[MSGC + j0 + q * 4] = *(float4*)&c[q * 4];
            }
        }
    }
}

// ---------------- launch ----------------
static cudaStream_t g_s2;
static cudaEvent_t  g_evFork, g_evJoin;
static bool         g_init = false;

extern "C" void kernel_launch(void* const* d_in, const int* in_sizes, int n_in,
                              void* d_out, int out_size)
{
    const float* feat = (const float*)d_in[0];
    const int*   src0 = (const int*)d_in[1];
    const int*   dst0 = (const int*)d_in[2];
    const int*   src1 = (const int*)d_in[3];
    const int*   dst1 = (const int*)d_in[4];
    const float* W_ih = (const float*)d_in[5];
    const float* W_hh = (const float*)d_in[6];
    const float* b_ih = (const float*)d_in[7];
    const float* b_hh = (const float*)d_in[8];
    float* out = (float*)d_out;

    if (!g_init) {
        cudaStreamCreateWithFlags(&g_s2, cudaStreamNonBlocking);
        cudaEventCreateWithFlags(&g_evFork, cudaEventDisableTiming);
        cudaEventCreateWithFlags(&g_evJoin, cudaEventDisableTiming);
        cudaFuncSetAttribute(gemm1_kernel, cudaFuncAttributeMaxDynamicSharedMemorySize,
                             G1_SMEM_BYTES);
        cudaFuncSetAttribute(gemm2_kernel, cudaFuncAttributeMaxDynamicSharedMemorySize,
                             G2_SMEM_BYTES);
        g_init = true;
    }

    void* degp = nullptr;
    cudaGetSymbolAddress(&degp, g_deg);
    cudaMemsetAsync(degp, 0, NSEG * sizeof(int), 0);

    // fork: prep + gemm1 on g_s2 (hidden under CSR build)
    cudaEventRecord(g_evFork, 0);
    cudaStreamWaitEvent(g_s2, g_evFork, 0);
    prep_kernel<<<192, GATESC, 0, g_s2>>>(W_ih, W_hh, b_ih, b_hh);
    {
        int nblocks = (N_NODESC + 63) / 64;
        gemm1_kernel<<<nblocks, 256, G1_SMEM_BYTES, g_s2>>>(feat);
    }
    cudaEventRecord(g_evJoin, g_s2);

    // stream 0: CSR build + aggregate
    count_kernel<<<(NEDGE_T + 255) / 256, 256>>>(dst0, dst1);
    scanA_kernel<<<SCAN_NB, SCAN_BS>>>();
    scanB_kernel<<<1, 32>>>();
    scanC_kernel<<<SCAN_NB, SCAN_BS>>>();
    fill_kernel<<<(NEDGE_T + 255) / 256, 256>>>(src0, dst0, src1, dst1);
    aggregate_kernel<<<(N_NODESC * 32 + 255) / 256, 256>>>(feat);

    // gemm2 needs g_gates (gemm1) + g_rst (aggregate)
    cudaStreamWaitEvent(0, g_evJoin, 0);
    {
        int nblocks = (N_NODESC + 63) / 64;
        gemm2_kernel<<<nblocks, 256, G2_SMEM_BYTES>>>(out);
    }
}

// round 7
// speedup vs baseline: 2.1977x; 1.0256x over previous
#include <cuda_runtime.h>
#include <cuda_fp16.h>
#include <math.h>
#include <stdint.h>

#define N_NODESC 50000
#define N_EDGESC 800000
#define HIDDENC  128
#define MSGC     64
#define GATESC   256
#define NSEG     (2 * N_NODESC)
#define NEDGE_T  (2 * N_EDGESC)
#define SCAN_BS  512
#define SCAN_NB  ((NSEG + SCAN_BS - 1) / SCAN_BS)   // 196

// ---------------- device scratch ----------------
__device__ int      g_deg[NSEG];
__device__ int      g_start[NSEG];
__device__ int      g_cursor[NSEG];
__device__ int      g_bsum[SCAN_NB];
__device__ int      g_ssorted[NEDGE_T];
__device__ float    g_rst[(size_t)N_NODESC * HIDDENC];
__device__ float    g_gates[(size_t)N_NODESC * GATESC];   // gemm1: bias + feat@Wih^T
__device__ uint32_t g_WTt[192 * GATESC];  // tf32 [k][gate]: rows 0..127 Wih^T, 128..191 Whh^T
__device__ float    g_bias[GATESC];
__device__ uint2    g_feat16[(size_t)N_NODESC * 32];   // fp16 feat: 32 uint2/row (4 halves each)

__device__ __forceinline__ uint32_t f2tf(float f) {
    uint32_t u;
    asm("cvt.rna.tf32.f32 %0, %1;" : "=r"(u) : "f"(f));
    return u;
}

__device__ __forceinline__ void mma_tf32(float& d0, float& d1, float& d2, float& d3,
                                         uint32_t a0, uint32_t a1, uint32_t a2, uint32_t a3,
                                         uint32_t b0, uint32_t b1)
{
    asm volatile("mma.sync.aligned.m16n8k8.row.col.f32.tf32.tf32.f32 "
                 "{%0,%1,%2,%3}, {%4,%5,%6,%7}, {%8,%9}, {%0,%1,%2,%3};\n"
                 : "+f"(d0), "+f"(d1), "+f"(d2), "+f"(d3)
                 : "r"(a0), "r"(a1), "r"(a2), "r"(a3), "r"(b0), "r"(b1));
}

// ---------------- convert feat -> fp16 ----------------
__global__ void __launch_bounds__(256) convert_kernel(const float* __restrict__ feat)
{
    int i = blockIdx.x * 256 + threadIdx.x;          // one uint2 (4 halves) per thread
    if (i >= N_NODESC * 32) return;
    float4 v = ((const float4*)feat)[i];
    __half2 h0 = __floats2half2_rn(v.x, v.y);
    __half2 h1 = __floats2half2_rn(v.z, v.w);
    uint2 u;
    u.x = *(uint32_t*)&h0;
    u.y = *(uint32_t*)&h1;
    g_feat16[i] = u;
}

// ---------------- prep: transpose W -> tf32, combine bias ----------------
__global__ void prep_kernel(const float* __restrict__ W_ih, const float* __restrict__ W_hh,
                            const float* __restrict__ b_ih, const float* __restrict__ b_hh)
{
    int r = threadIdx.x;   // gate 0..255
    int k = blockIdx.x;    // 0..191
    float v;
    if (k < HIDDENC) v = W_ih[r * HIDDENC + k];
    else             v = W_hh[r * MSGC + (k - HIDDENC)];
    g_WTt[k * GATESC + r] = f2tf(v);
    if (k == 0) g_bias[r] = b_ih[r] + b_hh[r];
}

// ---------------- CSR build ----------------
__global__ void __launch_bounds__(256) count_kernel(
    const int* __restrict__ dst0, const int* __restrict__ dst1)
{
    int e = blockIdx.x * 256 + threadIdx.x;
    if (e >= NEDGE_T) return;
    if (e < N_EDGESC) atomicAdd(&g_deg[dst0[e]], 1);
    else              atomicAdd(&g_deg[N_NODESC + dst1[e - N_EDGESC]], 1);
}

__global__ void __launch_bounds__(SCAN_BS) scanA_kernel()
{
    __shared__ int s[SCAN_BS];
    int tid = threadIdx.x;
    int i = blockIdx.x * SCAN_BS + tid;
    int v = (i < NSEG) ? g_deg[i] : 0;
    s[tid] = v;
    __syncthreads();
    #pragma unroll
    for (int off = 1; off < SCAN_BS; off <<= 1) {
        int x = (tid >= off) ? s[tid - off] : 0;
        __syncthreads();
        s[tid] += x;
        __syncthreads();
    }
    if (i < NSEG) g_start[i] = s[tid] - v;
    if (tid == SCAN_BS - 1) g_bsum[blockIdx.x] = s[tid];
}

__global__ void scanB_kernel()
{
    const int PER = (SCAN_NB + 31) / 32;
    int tid = threadIdx.x;
    int base = tid * PER;
    int vals[PER];
    int tot = 0;
    #pragma unroll
    for (int i = 0; i < PER; i++) {
        int idx = base + i;
        int t = (idx < SCAN_NB) ? g_bsum[idx] : 0;
        vals[i] = tot;
        tot += t;
    }
    int x = tot;
    #pragma unroll
    for (int off = 1; off < 32; off <<= 1) {
        int y = __shfl_up_sync(0xFFFFFFFFu, x, off);
        if (tid >= off) x += y;
    }
    int excl = x - tot;
    #pragma unroll
    for (int i = 0; i < PER; i++) {
        int idx = base + i;
        if (idx < SCAN_NB) g_bsum[idx] = excl + vals[i];
    }
}

__global__ void __launch_bounds__(SCAN_BS) scanC_kernel()
{
    int i = blockIdx.x * SCAN_BS + threadIdx.x;
    if (i < NSEG) {
        int v = g_start[i] + g_bsum[blockIdx.x];
        g_start[i] = v;
        g_cursor[i] = v;
    }
}

__global__ void __launch_bounds__(256) fill_kernel(
    const int* __restrict__ src0, const int* __restrict__ dst0,
    const int* __restrict__ src1, const int* __restrict__ dst1)
{
    int e = blockIdx.x * 256 + threadIdx.x;
    if (e >= NEDGE_T) return;
    int s, seg;
    if (e < N_EDGESC) { s = src0[e]; seg = dst0[e]; }
    else { int e2 = e - N_EDGESC; s = src1[e2]; seg = N_NODESC + dst1[e2]; }
    int pos = atomicAdd(&g_cursor[seg], 1);
    g_ssorted[pos] = s;
}

// ---------------- aggregate: warp per node, fp16 gather, fp32 accumulate -----
__device__ __forceinline__ void acc_h4(float4& s, uint2 u)
{
    float2 a = __half22float2(*(__half2*)&u.x);
    float2 b = __half22float2(*(__half2*)&u.y);
    s.x += a.x; s.y += a.y; s.z += b.x; s.w += b.y;
}

__global__ void __launch_bounds__(256) aggregate_kernel()
{
    int warp = (blockIdx.x * 256 + threadIdx.x) >> 5;
    int lane = threadIdx.x & 31;
    if (warp >= N_NODESC) return;

    float4 sum0 = make_float4(0.f, 0.f, 0.f, 0.f);
    float4 sum1 = make_float4(0.f, 0.f, 0.f, 0.f);
    int b0 = g_start[warp],            d0 = g_deg[warp];
    int b1 = g_start[N_NODESC + warp], d1 = g_deg[N_NODESC + warp];

    #pragma unroll 1
    for (int e = 0; e + 4 <= d0; e += 4) {
        int i0 = g_ssorted[b0 + e],     i1 = g_ssorted[b0 + e + 1];
        int i2 = g_ssorted[b0 + e + 2], i3 = g_ssorted[b0 + e + 3];
        uint2 v0 = g_feat16[(size_t)i0 * 32 + lane];
        uint2 v1 = g_feat16[(size_t)i1 * 32 + lane];
        uint2 v2 = g_feat16[(size_t)i2 * 32 + lane];
        uint2 v3 = g_feat16[(size_t)i3 * 32 + lane];
        acc_h4(sum0, v0); acc_h4(sum0, v1); acc_h4(sum0, v2); acc_h4(sum0, v3);
    }
    for (int e = d0 & ~3; e < d0; e++) {
        uint2 v = g_feat16[(size_t)g_ssorted[b0 + e] * 32 + lane];
        acc_h4(sum0, v);
    }
    #pragma unroll 1
    for (int e = 0; e + 4 <= d1; e += 4) {
        int i0 = g_ssorted[b1 + e],     i1 = g_ssorted[b1 + e + 1];
        int i2 = g_ssorted[b1 + e + 2], i3 = g_ssorted[b1 + e + 3];
        uint2 v0 = g_feat16[(size_t)i0 * 32 + lane];
        uint2 v1 = g_feat16[(size_t)i1 * 32 + lane];
        uint2 v2 = g_feat16[(size_t)i2 * 32 + lane];
        uint2 v3 = g_feat16[(size_t)i3 * 32 + lane];
        acc_h4(sum1, v0); acc_h4(sum1, v1); acc_h4(sum1, v2); acc_h4(sum1, v3);
    }
    for (int e = d1 & ~3; e < d1; e++) {
        uint2 v = g_feat16[(size_t)g_ssorted[b1 + e] * 32 + lane];
        acc_h4(sum1, v);
    }

    float i0f = 1.0f / (float)max(d0, 1);
    float i1f = 1.0f / (float)max(d1, 1);
    float has = (d0 > 0 ? 1.0f : 0.0f) + (d1 > 0 ? 1.0f : 0.0f);
    float ia = 1.0f / fmaxf(has, 1.0f);
    float4 r;
    r.x = (sum0.x * i0f + sum1.x * i1f) * ia;
    r.y = (sum0.y * i0f + sum1.y * i1f) * ia;
    r.z = (sum0.z * i0f + sum1.z * i1f) * ia;
    r.w = (sum0.w * i0f + sum1.w * i1f) * ia;
    *(float4*)(g_rst + (size_t)warp * HIDDENC + lane * 4) = r;
}

// ---------------- gemm1 (tf32 MMA): gates = bias + feat @ Wih^T --------------
#define G1_WPAD 264
#define G1_XPAD 132
#define G1_SW_OFF   0
#define G1_SX_OFF   (128 * G1_WPAD)
#define G1_SB_OFF   (G1_SX_OFF + 64 * G1_XPAD)
#define G1_SMEM_BYTES ((G1_SB_OFF + 256) * 4)

__global__ void __launch_bounds__(256, 1) gemm1_kernel(const float* __restrict__ feat)
{
    extern __shared__ uint32_t smu[];
    uint32_t* sW = smu + G1_SW_OFF;
    uint32_t* sX = smu + G1_SX_OFF;
    float*    sB = (float*)(smu + G1_SB_OFF);

    const int t    = threadIdx.x;
    const int lane = t & 31;
    const int wid  = t >> 5;
    const int n0   = blockIdx.x * 64;

    if (t < 256) sB[t] = g_bias[t];

    #pragma unroll
    for (int i = 0; i < 32; i++) {
        int idx = t + i * 256;
        int kk = idx >> 6, n4 = idx & 63;
        uint4 v = ((const uint4*)g_WTt)[idx];
        *(uint4*)&sW[kk * G1_WPAD + n4 * 4] = v;
    }
    #pragma unroll
    for (int i = 0; i < 8; i++) {
        int idx = t + i * 256;
        int nn = idx >> 5, c4 = idx & 31;
        int n = n0 + nn;
        float4 v = (n < N_NODESC) ? *(const float4*)(feat + (size_t)n * HIDDENC + c4 * 4)
                                  : make_float4(0.f, 0.f, 0.f, 0.f);
        uint32_t* d = &sX[nn * G1_XPAD + c4 * 4];
        d[0] = f2tf(v.x); d[1] = f2tf(v.y); d[2] = f2tf(v.z); d[3] = f2tf(v.w);
    }
    __syncthreads();

    const int wm = (wid >> 2) * 32;
    const int wn = (wid & 3) * 64;
    const int g  = lane >> 2;
    const int tq = lane & 3;

    float acc[2][8][4];
    #pragma unroll
    for (int mt = 0; mt < 2; mt++)
        #pragma unroll
        for (int nt = 0; nt < 8; nt++) {
            float b0 = sB[wn + nt * 8 + 2 * tq];
            float b1 = sB[wn + nt * 8 + 2 * tq + 1];
            acc[mt][nt][0] = b0; acc[mt][nt][1] = b1;
            acc[mt][nt][2] = b0; acc[mt][nt][3] = b1;
        }

    #pragma unroll 2
    for (int kk = 0; kk < 16; kk++) {
        int k0 = kk * 8;
        uint32_t a[2][4];
        #pragma unroll
        for (int mt = 0; mt < 2; mt++) {
            int mb = wm + mt * 16;
            a[mt][0] = sX[(mb + g) * G1_XPAD + k0 + tq];
            a[mt][1] = sX[(mb + g + 8) * G1_XPAD + k0 + tq];
            a[mt][2] = sX[(mb + g) * G1_XPAD + k0 + tq + 4];
            a[mt][3] = sX[(mb + g + 8) * G1_XPAD + k0 + tq + 4];
        }
        #pragma unroll
        for (int nt = 0; nt < 8; nt++) {
            int nb = wn + nt * 8 + g;
            uint32_t b0 = sW[(k0 + tq) * G1_WPAD + nb];
            uint32_t b1 = sW[(k0 + tq + 4) * G1_WPAD + nb];
            #pragma unroll
            for (int mt = 0; mt < 2; mt++)
                mma_tf32(acc[mt][nt][0], acc[mt][nt][1], acc[mt][nt][2], acc[mt][nt][3],
                         a[mt][0], a[mt][1], a[mt][2], a[mt][3], b0, b1);
        }
    }

    #pragma unroll
    for (int mt = 0; mt < 2; mt++) {
        int node = n0 + wm + mt * 16 + g;
        #pragma unroll
        for (int nt = 0; nt < 8; nt++) {
            int col = wn + nt * 8 + 2 * tq;
            if (node < N_NODESC)
                *(float2*)&g_gates[(size_t)node * GATESC + col] =
                    make_float2(acc[mt][nt][0], acc[mt][nt][1]);
            if (node + 8 < N_NODESC)
                *(float2*)&g_gates[(size_t)(node + 8) * GATESC + col] =
                    make_float2(acc[mt][nt][2], acc[mt][nt][3]);
        }
    }
}

// ---------------- gemm2 (tf32 MMA) + LSTM epilogue ----------------
#define G2_WPAD 264
#define G2_XPAD 68
#define G2_GPAD 260
#define G2_SW_OFF 0
#define G2_SX_OFF (64 * G2_WPAD)
#define G2_SMEM_U32 (G2_SX_OFF + 64 * G2_XPAD)
#define G2_SMEM_BYTES (G2_SMEM_U32 * 4)

__device__ __forceinline__ float sigf(float x) { return 1.0f / (1.0f + __expf(-x)); }

__global__ void __launch_bounds__(256, 2) gemm2_kernel(float* __restrict__ out)
{
    extern __shared__ uint32_t smu[];
    uint32_t* sW = smu + G2_SW_OFF;
    uint32_t* sX = smu + G2_SX_OFF;
    float*    sG = (float*)(smu + G2_SW_OFF);

    const int t    = threadIdx.x;
    const int lane = t & 31;
    const int wid  = t >> 5;
    const int n0   = blockIdx.x * 64;

    #pragma unroll
    for (int i = 0; i < 16; i++) {
        int idx = t + i * 256;
        int kk = idx >> 6, n4 = idx & 63;
        uint4 v = ((const uint4*)g_WTt)[(128 * GATESC) / 4 + idx];
        *(uint4*)&sW[kk * G2_WPAD + n4 * 4] = v;
    }
    #pragma unroll
    for (int i = 0; i < 4; i++) {
        int idx = t + i * 256;
        int nn = idx >> 4, c4 = idx & 15;
        int n = n0 + nn;
        float4 v = (n < N_NODESC) ? *(const float4*)(g_rst + (size_t)n * HIDDENC + c4 * 4)
                                  : make_float4(0.f, 0.f, 0.f, 0.f);
        uint32_t* d = &sX[nn * G2_XPAD + c4 * 4];
        d[0] = f2tf(v.x); d[1] = f2tf(v.y); d[2] = f2tf(v.z); d[3] = f2tf(v.w);
    }
    __syncthreads();

    const int wm = (wid >> 2) * 32;
    const int wn = (wid & 3) * 64;
    const int g  = lane >> 2;
    const int tq = lane & 3;

    float acc[2][8][4];
    #pragma unroll
    for (int mt = 0; mt < 2; mt++) {
        int node = n0 + wm + mt * 16 + g;
        #pragma unroll
        for (int nt = 0; nt < 8; nt++) {
            int col = wn + nt * 8 + 2 * tq;
            float2 c01 = (node < N_NODESC) ? *(const float2*)&g_gates[(size_t)node * GATESC + col]
                                           : make_float2(0.f, 0.f);
            float2 c23 = (node + 8 < N_NODESC) ? *(const float2*)&g_gates[(size_t)(node + 8) * GATESC + col]
                                               : make_float2(0.f, 0.f);
            acc[mt][nt][0] = c01.x; acc[mt][nt][1] = c01.y;
            acc[mt][nt][2] = c23.x; acc[mt][nt][3] = c23.y;
        }
    }

    #pragma unroll
    for (int kk = 0; kk < 8; kk++) {
        int k0 = kk * 8;
        uint32_t a[2][4];
        #pragma unroll
        for (int mt = 0; mt < 2; mt++) {
            int mb = wm + mt * 16;
            a[mt][0] = sX[(mb + g) * G2_XPAD + k0 + tq];
            a[mt][1] = sX[(mb + g + 8) * G2_XPAD + k0 + tq];
            a[mt][2] = sX[(mb + g) * G2_XPAD + k0 + tq + 4];
            a[mt][3] = sX[(mb + g + 8) * G2_XPAD + k0 + tq + 4];
        }
        #pragma unroll
        for (int nt = 0; nt < 8; nt++) {
            int nb = wn + nt * 8 + g;
            uint32_t b0 = sW[(k0 + tq) * G2_WPAD + nb];
            uint32_t b1 = sW[(k0 + tq + 4) * G2_WPAD + nb];
            #pragma unroll
            for (int mt = 0; mt < 2; mt++)
                mma_tf32(acc[mt][nt][0], acc[mt][nt][1], acc[mt][nt][2], acc[mt][nt][3],
                         a[mt][0], a[mt][1], a[mt][2], a[mt][3], b0, b1);
        }
    }
    __syncthreads();

    #pragma unroll
    for (int mt = 0; mt < 2; mt++) {
        int nn = wm + mt * 16 + g;
        #pragma unroll
        for (int nt = 0; nt < 8; nt++) {
            int col = wn + nt * 8 + 2 * tq;
            *(float2*)&sG[nn * G2_GPAD + col]       = make_float2(acc[mt][nt][0], acc[mt][nt][1]);
            *(float2*)&sG[(nn + 8) * G2_GPAD + col] = make_float2(acc[mt][nt][2], acc[mt][nt][3]);
        }
    }
    __syncthreads();

    {
        int nn = t >> 2;
        int j0 = (t & 3) * 16;
        int n  = n0 + nn;
        if (n < N_NODESC) {
            const float* gs = &sG[nn * G2_GPAD];
            const float* R  = g_rst + (size_t)n * HIDDENC + MSGC;
            float h[16], c[16];
            #pragma unroll
            for (int jj = 0; jj < 16; jj++) {
                int j = j0 + jj;
                float gi = gs[j];
                float gf = gs[MSGC + j];
                float gg = gs[2 * MSGC + j];
                float go = gs[3 * MSGC + j];
                float cc = sigf(gf) * R[j] + sigf(gi) * tanhf(gg);
                c[jj] = cc;
                h[jj] = sigf(go) * tanhf(cc);
            }
            float* orow = out + (size_t)n * HIDDENC;
            #pragma unroll
            for (int q = 0; q < 4; q++) {
                *(float4*)&orow[j0 + q * 4]        = *(float4*)&h[q * 4];
                *(float4*)&orow[MSGC + j0 + q * 4] = *(float4*)&c[q * 4];
            }
        }
    }
}

// ---------------- launch ----------------
static cudaStream_t g_s2;
static cudaEvent_t  g_evFork, g_evConv, g_evJoin;
static bool         g_init = false;

extern "C" void kernel_launch(void* const* d_in, const int* in_sizes, int n_in,
                              void* d_out, int out_size)
{
    const float* feat = (const float*)d_in[0];
    const int*   src0 = (const int*)d_in[1];
    const int*   dst0 = (const int*)d_in[2];
    const int*   src1 = (const int*)d_in[3];
    const int*   dst1 = (const int*)d_in[4];
    const float* W_ih = (const float*)d_in[5];
    const float* W_hh = (const float*)d_in[6];
    const float* b_ih = (const float*)d_in[7];
    const float* b_hh = (const float*)d_in[8];
    float* out = (float*)d_out;

    if (!g_init) {
        cudaStreamCreateWithFlags(&g_s2, cudaStreamNonBlocking);
        cudaEventCreateWithFlags(&g_evFork, cudaEventDisableTiming);
        cudaEventCreateWithFlags(&g_evConv, cudaEventDisableTiming);
        cudaEventCreateWithFlags(&g_evJoin, cudaEventDisableTiming);
        cudaFuncSetAttribute(gemm1_kernel, cudaFuncAttributeMaxDynamicSharedMemorySize,
                             G1_SMEM_BYTES);
        cudaFuncSetAttribute(gemm2_kernel, cudaFuncAttributeMaxDynamicSharedMemorySize,
                             G2_SMEM_BYTES);
        g_init = true;
    }

    void* degp = nullptr;
    cudaGetSymbolAddress(&degp, g_deg);
    cudaMemsetAsync(degp, 0, NSEG * sizeof(int), 0);

    // fork: convert + prep + gemm1 on g_s2 (hidden under CSR build)
    cudaEventRecord(g_evFork, 0);
    cudaStreamWaitEvent(g_s2, g_evFork, 0);
    convert_kernel<<<(N_NODESC * 32 + 255) / 256, 256, 0, g_s2>>>(feat);
    cudaEventRecord(g_evConv, g_s2);
    prep_kernel<<<192, GATESC, 0, g_s2>>>(W_ih, W_hh, b_ih, b_hh);
    {
        int nblocks = (N_NODESC + 63) / 64;
        gemm1_kernel<<<nblocks, 256, G1_SMEM_BYTES, g_s2>>>(feat);
    }
    cudaEventRecord(g_evJoin, g_s2);

    // stream 0: CSR build + aggregate
    count_kernel<<<(NEDGE_T + 255) / 256, 256>>>(dst0, dst1);
    scanA_kernel<<<SCAN_NB, SCAN_BS>>>();
    scanB_kernel<<<1, 32>>>();
    scanC_kernel<<<SCAN_NB, SCAN_BS>>>();
    fill_kernel<<<(NEDGE_T + 255) / 256, 256>>>(src0, dst0, src1, dst1);

    // aggregate needs g_feat16
    cudaStreamWaitEvent(0, g_evConv, 0);
    aggregate_kernel<<<(N_NODESC * 32 + 255) / 256, 256>>>();

    // gemm2 needs g_gates (gemm1) + g_rst (aggregate)
    cudaStreamWaitEvent(0, g_evJoin, 0);
    {
        int nblocks = (N_NODESC + 63) / 64;
        gemm2_kernel<<<nblocks, 256, G2_SMEM_BYTES>>>(out);
    }
}